// round 6
// baseline (speedup 1.0000x reference)
#include <cuda_runtime.h>
#include <math.h>

// Problem constants (fixed by the reference)
#define B_DIM 2
#define L_DIM 2048
#define V_DIM 32001
#define ROWS (B_DIM * L_DIM)                       // 4096
#define REV_FLOATS (131076096LL)                   // ROWS * V_DIM, divisible by 8
#define N8 (REV_FLOATS / 8)                        // 16384512 32-byte units

#define G_LOGIC 16                                 // logic blocks (4096 threads)
#define G_FILL 4096                                // fill blocks
#define FILL_CHUNK ((N8 + G_FILL - 1) / G_FILL)    // 4001 F8 per block

struct alignas(32) F8 { float4 a, b; };

__device__ int g_cnt = 0;          // masked-row worklist (reset by post kernel)
__device__ int g_rows[ROWS];

__device__ __forceinline__ float gumbel_noise(float u) {
    const float GEPS = 1e-6f;
    return GEPS - logf(GEPS + (1.0f - GEPS) * u);
}

// One launch: blocks [0,16) = row logic; blocks [16, 16+G_FILL) = flat zero fill.
// The logic's fast path (x_new) and even the masked-row gumbel sample are
// independent of the fill; only masked-row rev writes are deferred to the
// post kernel (which runs after all fill writes).
__global__ __launch_bounds__(256)
void fused_kernel(const float* __restrict__ outp,   // [B,L,V]
                  const int* __restrict__ xt,       // [B,L]
                  const float* __restrict__ t,      // [B]
                  const float* __restrict__ step_p, // [1]
                  const float* __restrict__ u,      // [B,L,V]
                  float* __restrict__ x_new,        // [B*L]
                  float* __restrict__ rev)          // [B,L,V]
{
    const int tid = threadIdx.x;

    if (blockIdx.x >= G_LOGIC) {
        // ---- flat fill: contiguous 128KB chunk per block, 32B stores ----
        const long long fb = blockIdx.x - G_LOGIC;
        long long base = fb * FILL_CHUNK;
        long long end  = base + FILL_CHUNK;
        if (end > N8) end = N8;
        F8 z; z.a = make_float4(0.f, 0.f, 0.f, 0.f); z.b = z.a;
        F8* __restrict__ p = (F8*)rev;
        for (long long i = base + tid; i < end; i += 256) p[i] = z;
        return;
    }

    // ---- row logic: thread-per-row ----
    const int row = blockIdx.x * 256 + tid;   // 0..4095
    const int mask_tok = V_DIM - 1;

    __shared__ int s_count;
    __shared__ int s_rows[256];
    if (tid == 0) s_count = 0;
    __syncthreads();

    int x = xt[row];
    if (x == -1) x = mask_tok;

    if (x != mask_tok) {
        // rev row is exactly zero; argmax of xt_prob/gnoise is deterministically x
        x_new[row] = (float)x;
    } else {
        int slot = atomicAdd(&s_count, 1);
        s_rows[slot] = row;
        int gslot = atomicAdd(&g_cnt, 1);      // defer rev-row write
        g_rows[gslot] = row;
    }
    __syncthreads();

    const int cnt = s_count;
    if (cnt == 0) return;

    // ---- cooperative gumbel sample for masked rows (register/smem only;
    //      no rev writes here — those happen in the post kernel) ----
    __shared__ float s_sum[256];
    __shared__ float s_val[256];
    __shared__ int   s_idx[256];

    const float EPS  = 1e-3f;
    const float step = *step_p;

    for (int m = 0; m < cnt; m++) {
        const int mrow = s_rows[m];
        const int b = mrow / L_DIM;
        const float sigma = (1.0f - EPS) / (1.0f - (1.0f - EPS) * t[b]);

        const float* __restrict__ orow = outp + (long long)mrow * V_DIM;
        const float* __restrict__ urow = u    + (long long)mrow * V_DIM;

        float sum = 0.0f;
        float best_v = -INFINITY;
        int   best_i = V_DIM;

        for (int v = tid; v < V_DIM; v += 256) {
            if (v == mask_tok) continue;
            float s = expf(orow[v]);
            sum += s;
            float r = sigma * s;
            float g = gumbel_noise(urow[v]);
            float ratio = (step * r) / g;
            if (ratio > best_v || (ratio == best_v && v < best_i)) {
                best_v = ratio;
                best_i = v;
            }
        }

        s_sum[tid] = sum;
        s_val[tid] = best_v;
        s_idx[tid] = best_i;
        __syncthreads();

        for (int off = 128; off > 0; off >>= 1) {
            if (tid < off) {
                s_sum[tid] += s_sum[tid + off];
                float ov = s_val[tid + off];
                int   oi = s_idx[tid + off];
                if (ov > s_val[tid] || (ov == s_val[tid] && oi < s_idx[tid])) {
                    s_val[tid] = ov;
                    s_idx[tid] = oi;
                }
            }
            __syncthreads();
        }

        if (tid == 0) {
            float rd = sigma * (-s_sum[0]);        // diagonal rev_rate
            float prob = 1.0f + step * rd;         // oh=1 at diagonal
            float g = gumbel_noise(urow[mask_tok]);
            float ratio = prob / g;
            int res = s_idx[0];
            if (ratio > s_val[0]) res = mask_tok;  // tie -> off-diag (lower idx)
            x_new[mrow] = (res == mask_tok) ? -1.0f : (float)res;
        }
        __syncthreads();
    }
}

// Post kernel: one block. Writes rev rows for masked rows (after fill),
// then resets the worklist counter for the next graph replay.
__global__ __launch_bounds__(1024)
void heavy_rev_kernel(const float* __restrict__ outp,
                      const float* __restrict__ t,
                      float* __restrict__ rev)
{
    const int tid = threadIdx.x;
    const int mask_tok = V_DIM - 1;
    const float EPS = 1e-3f;

    __shared__ int s_cnt;
    __shared__ float s_red[1024];
    if (tid == 0) s_cnt = g_cnt;
    __syncthreads();
    const int cnt = s_cnt;

    for (int m = 0; m < cnt; m++) {
        const int row = g_rows[m];
        const int b = row / L_DIM;
        const float sigma = (1.0f - EPS) / (1.0f - (1.0f - EPS) * t[b]);
        const float* __restrict__ orow = outp + (long long)row * V_DIM;
        float* __restrict__       rrow = rev  + (long long)row * V_DIM;

        float sum = 0.0f;
        for (int v = tid; v < V_DIM; v += 1024) {
            if (v == mask_tok) continue;
            float s = expf(orow[v]);
            sum += s;
            rrow[v] = sigma * s;
        }
        s_red[tid] = sum;
        __syncthreads();
        for (int off = 512; off > 0; off >>= 1) {
            if (tid < off) s_red[tid] += s_red[tid + off];
            __syncthreads();
        }
        if (tid == 0) rrow[mask_tok] = -sigma * s_red[0];
        __syncthreads();
    }

    if (tid == 0) g_cnt = 0;   // ready for next replay (deterministic)
}

extern "C" void kernel_launch(void* const* d_in, const int* in_sizes, int n_in,
                              void* d_out, int out_size) {
    const float* outp   = (const float*)d_in[0]; // [B,L,V] f32
    const int*   xt     = (const int*)  d_in[1]; // [B,L]   i32
    const float* t      = (const float*)d_in[2]; // [B]     f32
    const float* step_p = (const float*)d_in[3]; // scalar  f32
    const float* u      = (const float*)d_in[4]; // [B,L,V] f32

    float* x_new = (float*)d_out;                  // first B*L elements
    float* rev   = (float*)d_out + ROWS;           // then B*L*V elements

    fused_kernel<<<G_LOGIC + G_FILL, 256>>>(outp, xt, t, step_p, u, x_new, rev);
    heavy_rev_kernel<<<1, 1024>>>(outp, t, rev);
}